// round 2
// baseline (speedup 1.0000x reference)
#include <cuda_runtime.h>
#include <cuda_fp16.h>

// ---------------------------------------------------------------------------
// BlocCircLinear via legacy tensor cores (mma.sync m16n8k16, f16 in / f32 acc).
// Toolchain compiles at compute_103 (no 'a'), so tcgen05 is unavailable.
//
// Formulation: out^T  ->  D[b=32, 8192] = X[32, 8192] @ W^T, where
//   W[m,k] = blocks[(mi-nj)%512][p][q],  m=16*mi+p, k=16*nj+q.
// A side = x (2 m-frags, reused by every n-frag).  B side = W^T fragments
// ldmatrix'd straight out of a staged block table (95 blocks per CTA),
// exploiting circulant structure: no W materialization at all.
// Grid: 16 N-tiles (512 cols) x 8 K-splits (K=1024) = 128 CTAs, 256 thr.
// All operands staged once per CTA -> single __syncthreads, pure MMA loop.
// ---------------------------------------------------------------------------

#define BATCH   32
#define NBLK    512
#define DIM     8192
#define NTILES  16        // 8192 / 512 output cols
#define KSPLIT  8         // K split -> 1024 per CTA
#define KCTA    1024
#define JSTEPS  64        // KCTA / 16
#define THREADS 256

#define XS_STR   1032                 // halves per x row (1024 + 8 pad)
#define BLK_N    95                   // blocks staged per CTA
#define SMEM_XS  (BLK_N * 512)        // 48640 B (128B-aligned: 380*128)
#define SMEM_TOT (SMEM_XS + BATCH * XS_STR * 2)   // 48640 + 66048 = 114688

__device__ __half g_xh[BATCH * DIM];             // x in f16  [32][8192]
__device__ __half g_blkh[NBLK * 256];            // blocks f16 [512][16][16]
__device__ float  g_part[KSPLIT][BATCH * DIM];   // partials  [8][32][8192]

static __device__ __forceinline__ unsigned swzb(unsigned off) {
    return off ^ ((off >> 3) & 0x70);            // SW128-style, block-relative
}
static __device__ __forceinline__ unsigned smem_u32(const void* p) {
    return (unsigned)__cvta_generic_to_shared(p);
}
static __device__ __forceinline__ void cp16(unsigned dst, const void* src) {
    asm volatile("cp.async.cg.shared.global [%0], [%1], 16;"
                 :: "r"(dst), "l"(src) : "memory");
}
static __device__ __forceinline__ void ldsm4(unsigned* r, unsigned addr) {
    asm volatile("ldmatrix.sync.aligned.m8n8.x4.shared.b16 {%0,%1,%2,%3}, [%4];"
                 : "=r"(r[0]), "=r"(r[1]), "=r"(r[2]), "=r"(r[3]) : "r"(addr));
}
static __device__ __forceinline__ void mma16816(float* c, const unsigned* a,
                                                unsigned b0, unsigned b1) {
    asm volatile(
        "mma.sync.aligned.m16n8k16.row.col.f32.f16.f16.f32 "
        "{%0,%1,%2,%3}, {%4,%5,%6,%7}, {%8,%9}, {%0,%1,%2,%3};"
        : "+f"(c[0]), "+f"(c[1]), "+f"(c[2]), "+f"(c[3])
        : "r"(a[0]), "r"(a[1]), "r"(a[2]), "r"(a[3]), "r"(b0), "r"(b1));
}

// ---------------------------------------------------------------------------
__global__ void __launch_bounds__(256) convert_kernel(
    const float* __restrict__ x, const float* __restrict__ blk)
{
    int i = blockIdx.x * 256 + threadIdx.x;
    if (i < BATCH * DIM)  g_xh[i]   = __float2half(x[i]);
    if (i < NBLK * 256)   g_blkh[i] = __float2half(blk[i]);
}

// ---------------------------------------------------------------------------
extern __shared__ __align__(1024) char smem[];

__global__ void __launch_bounds__(THREADS, 1) bc_mma_kernel()
{
    const int tid  = threadIdx.x;
    const int wid  = tid >> 5;
    const int lane = tid & 31;
    const int T    = blockIdx.x & (NTILES - 1);   // output col tile (512 cols)
    const int ks   = blockIdx.x >> 4;             // K split index
    const int smin = (T * 32 - ks * 64 - 63) & (NBLK - 1);

    char*   blk = smem;                           // 95 blocks, swizzled
    __half* xs  = (__half*)(smem + SMEM_XS);      // x[32][1032]

    // ---- stage x chunk: 32 rows x 1024 halves (4096 x 16B) ----
    {
        const char* xsrc = (const char*)g_xh;
        for (int i = tid; i < 4096; i += THREADS) {
            int row = i >> 7, c = i & 127;
            cp16(smem_u32(xs + row * XS_STR) + c * 16,
                 xsrc + row * (DIM * 2) + ks * 2048 + c * 16);
        }
        // ---- stage 95 blocks (3040 x 16B), swizzled within each 512B ----
        const char* bsrc = (const char*)g_blkh;
        for (int i = tid; i < BLK_N * 32; i += THREADS) {
            int d = i >> 5, w = i & 31;
            int s = (smin + d) & (NBLK - 1);
            cp16(smem_u32(blk) + d * 512 + swzb(w * 16),
                 bsrc + s * 512 + w * 16);
        }
        asm volatile("cp.async.commit_group;\n\tcp.async.wait_group 0;" ::: "memory");
        __syncthreads();
    }

    // ---- per-warp lane-invariant addressing ----
    const int a0 = wid * 4;                       // warp's first block-row (of 32)
    // A (x) ldmatrix lane address: tiles (m0-7,k0-7)(m8-15,k0-7)(m0-7,k8-15)(m8-15,k8-15)
    unsigned arow = (unsigned)(lane & 15);
    unsigned kadd = (unsigned)((lane >> 4) * 8);
    unsigned aA0 = smem_u32(xs) + arow * (XS_STR * 2) + kadd * 2;
    unsigned aA1 = aA0 + 16 * (XS_STR * 2);
    // B (block) ldmatrix lane offset within a 512B block:
    // tiles (p0-7,q0-7)(p0-7,q8-15)(p8-15,q0-7)(p8-15,q8-15)
    unsigned pr   = (unsigned)(((lane >> 4) & 1) * 8 + (lane & 7));
    unsigned koff = (unsigned)(((lane >> 3) & 1) * 16);
    unsigned bl   = swzb(pr * 32 + koff);
    unsigned bB   = smem_u32(blk) + (unsigned)((a0 + 63) * 512) + bl;

    float acc[2][8][4] = {};

#pragma unroll 2
    for (int j = 0; j < JSTEPS; ++j) {
        unsigned A0[4], A1[4], B[4][4];
        ldsm4(A0, aA0);
        ldsm4(A1, aA1);
#pragma unroll
        for (int r = 0; r < 4; ++r) ldsm4(B[r], bB + (unsigned)(r * 512));
#pragma unroll
        for (int r = 0; r < 4; ++r) {
            mma16816(acc[0][2 * r],     A0, B[r][0], B[r][1]);
            mma16816(acc[1][2 * r],     A1, B[r][0], B[r][1]);
            mma16816(acc[0][2 * r + 1], A0, B[r][2], B[r][3]);
            mma16816(acc[1][2 * r + 1], A1, B[r][2], B[r][3]);
        }
        aA0 += 32; aA1 += 32;      // k advance: 16 halves
        bB  -= 512;                // circulant: s index drops by 1 per k-block
    }

    // ---- epilogue: write f32 partials [b][col] ----
    const int q  = lane & 3;
    const int rw = lane >> 2;
    float* part = g_part[ks];
#pragma unroll
    for (int m = 0; m < 2; ++m) {
#pragma unroll
        for (int nf = 0; nf < 8; ++nf) {
            int col = T * 512 + (a0 + (nf >> 1)) * 16 + (nf & 1) * 8 + q * 2;
            int b0  = m * 16 + rw;
            *reinterpret_cast<float2*>(&part[b0 * DIM + col]) =
                make_float2(acc[m][nf][0], acc[m][nf][1]);
            *reinterpret_cast<float2*>(&part[(b0 + 8) * DIM + col]) =
                make_float2(acc[m][nf][2], acc[m][nf][3]);
        }
    }
}

// ---------------------------------------------------------------------------
__global__ void __launch_bounds__(256) reduce_kernel(float* __restrict__ out)
{
    int i = blockIdx.x * 256 + threadIdx.x;       // i = b*8192 + m
    float v = 0.f;
#pragma unroll
    for (int ksp = 0; ksp < KSPLIT; ++ksp) v += g_part[ksp][i];
    out[i] = v;
}

// ---------------------------------------------------------------------------
extern "C" void kernel_launch(void* const* d_in, const int* in_sizes, int n_in,
                              void* d_out, int out_size)
{
    const float* x   = (const float*)d_in[0];
    const float* blk = (const float*)d_in[1];
    float* out = (float*)d_out;

    cudaFuncSetAttribute(bc_mma_kernel,
                         cudaFuncAttributeMaxDynamicSharedMemorySize, SMEM_TOT);

    convert_kernel<<<1024, 256>>>(x, blk);
    bc_mma_kernel<<<NTILES * KSPLIT, THREADS, SMEM_TOT>>>();
    reduce_kernel<<<1024, 256>>>(out);
}

// round 3
// speedup vs baseline: 1.0295x; 1.0295x over previous
#include <cuda_runtime.h>
#include <cuda_fp16.h>

// ---------------------------------------------------------------------------
// BlocCircLinear via mma.sync m16n8k16 (f16 in / f32 acc), compute_103-safe.
//   D[b=32, 8192] = X[32, 8192] @ W^T,  W block-circulant from blocks[512][16][16].
// A side = x (2 m-frags reused by all n-frags). B side = blocks ldmatrix'd
// straight from a staged table. Circulant shift => per k-step only ONE new
// B fragment per warp (register rotation), 3 KB -> 1.5 KB smem/j/warp.
// Software-pipelined: next-step LDSMs issued before current MMAs.
// ---------------------------------------------------------------------------

#define BATCH   32
#define NBLK    512
#define DIM     8192
#define NTILES  16        // 8192 / 512 output cols
#define KSPLIT  8         // K split -> 1024 per CTA
#define JSTEPS  64        // 1024 / 16
#define THREADS 256

#define XS_STR   1032                       // halves per x row (1024 + 8 pad)
#define BLK_N    95                         // blocks staged per CTA
#define PAD_LO   512                        // underflow pad (prefetch d = -1)
#define PAD_HI   1024                       // overflow pad (A prefetch @ j=63)
#define OFF_BLK  PAD_LO
#define OFF_XS   (PAD_LO + BLK_N * 512)     // 512 + 48640
#define SMEM_TOT (OFF_XS + BATCH * XS_STR * 2 + PAD_HI)   // 116224

__device__ __half g_xh[BATCH * DIM];             // x in f16  [32][8192]
__device__ __half g_blkh[NBLK * 256];            // blocks f16 [512][16][16]
__device__ float  g_part[KSPLIT][BATCH * DIM];   // partials  [8][32][8192]

static __device__ __forceinline__ unsigned swzb(unsigned off) {
    return off ^ ((off >> 3) & 0x70);
}
static __device__ __forceinline__ unsigned smem_u32(const void* p) {
    return (unsigned)__cvta_generic_to_shared(p);
}
static __device__ __forceinline__ void cp16(unsigned dst, const void* src) {
    asm volatile("cp.async.cg.shared.global [%0], [%1], 16;"
                 :: "r"(dst), "l"(src) : "memory");
}
static __device__ __forceinline__ void ldsm4(unsigned* r, unsigned addr) {
    asm volatile("ldmatrix.sync.aligned.m8n8.x4.shared.b16 {%0,%1,%2,%3}, [%4];"
                 : "=r"(r[0]), "=r"(r[1]), "=r"(r[2]), "=r"(r[3]) : "r"(addr));
}
static __device__ __forceinline__ void mma16816(float* c, const unsigned* a,
                                                unsigned b0, unsigned b1) {
    asm volatile(
        "mma.sync.aligned.m16n8k16.row.col.f32.f16.f16.f32 "
        "{%0,%1,%2,%3}, {%4,%5,%6,%7}, {%8,%9}, {%0,%1,%2,%3};"
        : "+f"(c[0]), "+f"(c[1]), "+f"(c[2]), "+f"(c[3])
        : "r"(a[0]), "r"(a[1]), "r"(a[2]), "r"(a[3]), "r"(b0), "r"(b1));
}

// ---------------------------------------------------------------------------
// Kernel 1: fp32 -> fp16, 8 elems/thread, vectorized.
//   x: 262144 elems -> 32768 threads; blocks: 131072 -> 16384 threads.
// ---------------------------------------------------------------------------
__global__ void __launch_bounds__(256) convert_kernel(
    const float* __restrict__ x, const float* __restrict__ blk)
{
    int i = blockIdx.x * 256 + threadIdx.x;
    const float4* src;
    uint4* dst;
    if (i < 32768) {
        src = reinterpret_cast<const float4*>(x) + i * 2;
        dst = reinterpret_cast<uint4*>(g_xh) + i;
    } else {
        int j = i - 32768;            // < 16384
        src = reinterpret_cast<const float4*>(blk) + j * 2;
        dst = reinterpret_cast<uint4*>(g_blkh) + j;
    }
    float4 a = src[0], b = src[1];
    __half2 h0 = __float22half2_rn(make_float2(a.x, a.y));
    __half2 h1 = __float22half2_rn(make_float2(a.z, a.w));
    __half2 h2 = __float22half2_rn(make_float2(b.x, b.y));
    __half2 h3 = __float22half2_rn(make_float2(b.z, b.w));
    uint4 o;
    o.x = *reinterpret_cast<unsigned*>(&h0);
    o.y = *reinterpret_cast<unsigned*>(&h1);
    o.z = *reinterpret_cast<unsigned*>(&h2);
    o.w = *reinterpret_cast<unsigned*>(&h3);
    *dst = o;
}

// ---------------------------------------------------------------------------
// Kernel 2: block-circulant GEMM, grid = NTILES * KSPLIT = 128 CTAs.
// ---------------------------------------------------------------------------
extern __shared__ __align__(1024) char smem[];

__global__ void __launch_bounds__(THREADS, 1) bc_mma_kernel()
{
    const int tid  = threadIdx.x;
    const int wid  = tid >> 5;
    const int lane = tid & 31;
    const int T    = blockIdx.x & (NTILES - 1);
    const int ks   = blockIdx.x >> 4;
    const int smin = (T * 32 - ks * 64 - 63) & (NBLK - 1);

    char*   blk = smem + OFF_BLK;
    __half* xs  = (__half*)(smem + OFF_XS);

    // ---- stage x chunk (32 x 1024 halves) + 95 blocks ----
    {
        const char* xsrc = (const char*)g_xh;
        for (int i = tid; i < 4096; i += THREADS) {
            int row = i >> 7, c = i & 127;
            cp16(smem_u32(xs + row * XS_STR) + c * 16,
                 xsrc + row * (DIM * 2) + ks * 2048 + c * 16);
        }
        const char* bsrc = (const char*)g_blkh;
        for (int i = tid; i < BLK_N * 32; i += THREADS) {
            int d = i >> 5, w = i & 31;
            int s = (smin + d) & (NBLK - 1);
            cp16(smem_u32(blk) + d * 512 + swzb(w * 16),
                 bsrc + s * 512 + w * 16);
        }
        asm volatile("cp.async.commit_group;\n\tcp.async.wait_group 0;" ::: "memory");
        __syncthreads();
    }

    // ---- lane-invariant ldmatrix addresses ----
    const int a0 = wid * 4;                       // warp's first block-col
    unsigned arow = (unsigned)(lane & 15);
    unsigned kadd = (unsigned)((lane >> 4) * 8);
    unsigned aA0 = smem_u32(xs) + arow * (XS_STR * 2) + kadd * 2;
    unsigned aA1 = aA0 + 16 * (XS_STR * 2);
    unsigned pr   = (unsigned)(((lane >> 4) & 1) * 8 + (lane & 7));
    unsigned koff = (unsigned)(((lane >> 3) & 1) * 16);
    unsigned bl   = swzb(pr * 32 + koff);
    unsigned bbase = smem_u32(blk) + bl;

    float acc[2][8][4] = {};

    // ---- preload j=0 fragments ----
    unsigned A0[4], A1[4], Bf[4][4];
    ldsm4(A0, aA0);
    ldsm4(A1, aA1);
#pragma unroll
    for (int r = 0; r < 4; ++r)
        ldsm4(Bf[r], bbase + (unsigned)((a0 + 63 + r) * 512));
    unsigned bPre = bbase + (unsigned)((a0 + 62) * 512);  // next-step new frag

#pragma unroll 4
    for (int j = 0; j < JSTEPS; ++j) {
        // prefetch next step (overreads land in smem pads; values unused)
        unsigned An0[4], An1[4], Bn[4];
        ldsm4(An0, aA0 + 32);
        ldsm4(An1, aA1 + 32);
        ldsm4(Bn, bPre);

        // 16 MMAs on current fragments
#pragma unroll
        for (int r = 0; r < 4; ++r) {
            mma16816(acc[0][2 * r],     A0, Bf[r][0], Bf[r][1]);
            mma16816(acc[1][2 * r],     A1, Bf[r][0], Bf[r][1]);
            mma16816(acc[0][2 * r + 1], A0, Bf[r][2], Bf[r][3]);
            mma16816(acc[1][2 * r + 1], A1, Bf[r][2], Bf[r][3]);
        }

        // rotate: window shifts by one block per k-step (circulant)
#pragma unroll
        for (int t = 0; t < 4; ++t) {
            Bf[3][t] = Bf[2][t];
            Bf[2][t] = Bf[1][t];
            Bf[1][t] = Bf[0][t];
            Bf[0][t] = Bn[t];
            A0[t] = An0[t];
            A1[t] = An1[t];
        }
        aA0 += 32; aA1 += 32;
        bPre -= 512;
    }

    // ---- epilogue: f32 partials [b][col] ----
    const int q  = lane & 3;
    const int rw = lane >> 2;
    float* part = g_part[ks];
#pragma unroll
    for (int m = 0; m < 2; ++m) {
#pragma unroll
        for (int nf = 0; nf < 8; ++nf) {
            int col = T * 512 + (a0 + (nf >> 1)) * 16 + (nf & 1) * 8 + q * 2;
            int b0  = m * 16 + rw;
            *reinterpret_cast<float2*>(&part[b0 * DIM + col]) =
                make_float2(acc[m][nf][0], acc[m][nf][1]);
            *reinterpret_cast<float2*>(&part[(b0 + 8) * DIM + col]) =
                make_float2(acc[m][nf][2], acc[m][nf][3]);
        }
    }
}

// ---------------------------------------------------------------------------
// Kernel 3: reduce partials (float4), mostly L2-resident.
// ---------------------------------------------------------------------------
__global__ void __launch_bounds__(256) reduce_kernel(float* __restrict__ out)
{
    int i = blockIdx.x * 256 + threadIdx.x;       // 65536 threads, float4 each
    float4 v = reinterpret_cast<const float4*>(g_part[0])[i];
#pragma unroll
    for (int ksp = 1; ksp < KSPLIT; ++ksp) {
        float4 p = reinterpret_cast<const float4*>(g_part[ksp])[i];
        v.x += p.x; v.y += p.y; v.z += p.z; v.w += p.w;
    }
    reinterpret_cast<float4*>(out)[i] = v;
}

// ---------------------------------------------------------------------------
extern "C" void kernel_launch(void* const* d_in, const int* in_sizes, int n_in,
                              void* d_out, int out_size)
{
    const float* x   = (const float*)d_in[0];
    const float* blk = (const float*)d_in[1];
    float* out = (float*)d_out;

    cudaFuncSetAttribute(bc_mma_kernel,
                         cudaFuncAttributeMaxDynamicSharedMemorySize, SMEM_TOT);

    convert_kernel<<<192, 256>>>(x, blk);                 // 49152 threads
    bc_mma_kernel<<<NTILES * KSPLIT, THREADS, SMEM_TOT>>>();
    reduce_kernel<<<256, 256>>>(out);                     // 65536 threads
}